// round 14
// baseline (speedup 1.0000x reference)
#include <cuda_runtime.h>
#include <cuda_bf16.h>
#include <cstdint>

#define BB 128
#define TT 256
#define DD 64
#define HH 512
#define NBLK 128
#define NTHR 512
#define PRED_SZ (BB*(TT-1)*DD)

// smem: weights (bf16 hi/lo) + Wm column + epilogue partial buffer
#define W1_STRIDE 584
#define W2_STRIDE 1032
#define SM_W1HI 0
#define SM_W1LO (SM_W1HI + 16*W1_STRIDE*2)
#define SM_W2HI (SM_W1LO + 16*W1_STRIDE*2)
#define SM_W2LO (SM_W2HI + 16*W2_STRIDE*2)
#define SM_WP   (SM_W2LO + 16*W2_STRIDE*2)
#define SM_PART (SM_WP + 2048)
#define SM_TOTAL (SM_PART + 8192)

// h state in GLOBAL MEMORY in mma-fragment layout.
__device__ __align__(16) unsigned short g_h1h[2][BB*HH], g_h1l[2][BB*HH];
__device__ __align__(16) unsigned short g_h2h[2][BB*HH], g_h2l[2][BB*HH];
__device__ __align__(16) float g_h2f[2][BB*HH];
__device__ __align__(16) unsigned short g_curh[BB*DD], g_curl[BB*DD];
__device__ unsigned int g_bar;
__device__ int g_cntA, g_cntB, g_cntC;   // reset to 0 at end of every launch

__device__ __forceinline__ uint32_t smem_u32(const void* p) {
    uint32_t a;
    asm("{ .reg .u64 t; cvta.to.shared.u64 t, %1; cvt.u32.u64 %0, t; }" : "=r"(a) : "l"(p));
    return a;
}
__device__ __forceinline__ void ldsm4(uint32_t r[4], uint32_t addr) {
    asm volatile("ldmatrix.sync.aligned.m8n8.x4.shared.b16 {%0,%1,%2,%3}, [%4];"
        : "=r"(r[0]), "=r"(r[1]), "=r"(r[2]), "=r"(r[3]) : "r"(addr));
}
__device__ __forceinline__ void mma_bf16(float c[4], const uint32_t a[4], uint32_t b0, uint32_t b1) {
    asm volatile("mma.sync.aligned.m16n8k16.row.col.f32.bf16.bf16.f32 "
        "{%0,%1,%2,%3}, {%4,%5,%6,%7}, {%8,%9}, {%0,%1,%2,%3};"
        : "+f"(c[0]), "+f"(c[1]), "+f"(c[2]), "+f"(c[3])
        : "r"(a[0]), "r"(a[1]), "r"(a[2]), "r"(a[3]), "r"(b0), "r"(b1));
}
__device__ __forceinline__ void bf16split(float v, unsigned short &hi, unsigned short &lo) {
    __nv_bfloat16 hb = __float2bfloat16(v);
    hi = __bfloat16_as_ushort(hb);
    lo = __bfloat16_as_ushort(__float2bfloat16(v - __bfloat162float(hb)));
}
__device__ __forceinline__ int hfrag_idx(int r, int c) {
    int rb = r >> 4, kt = c >> 4;
    int l = ((r & 7) << 2) | ((c >> 1) & 3);
    int j = ((r >> 3) & 1) | (((c >> 3) & 1) << 1);
    return (((rb*32 + kt)*32 + l) << 3) + j*2 + (c & 1);
}
__device__ __forceinline__ int cfrag_idx(int r, int c) {
    int rb = r >> 4, kt = c >> 4;
    int l = ((r & 7) << 2) | ((c >> 1) & 3);
    int j = ((r >> 3) & 1) | (((c >> 3) & 1) << 1);
    return (((rb*4 + kt)*32 + l) << 3) + j*2 + (c & 1);
}

__device__ __forceinline__ void grid_barrier() {
    __syncthreads();
    if (threadIdx.x == 0) {
        __threadfence();
        unsigned my = atomicAdd(&g_bar, 1u) + 1u;
        unsigned target = my + (NBLK - 1u) - ((my - 1u) % NBLK);
        while ((int)(*(volatile unsigned*)&g_bar - target) < 0) __nanosleep(32);
        __threadfence();
    }
    __syncthreads();
}

__device__ __forceinline__ void poll_cnt(int* cnt, int target) {
    if ((threadIdx.x & 31) == 0) {
        volatile int* c = (volatile int*)cnt;
        while (*c < target) __nanosleep(32);
    }
    __syncwarp();
    __threadfence();
}

// load this warp's HALF of a 64-k chunk (2 k-tiles) into registers
__device__ __forceinline__ void issue_half(uint4 Ah[2], uint4 Al[2],
    const unsigned short* __restrict__ gh, const unsigned short* __restrict__ gl,
    int nkt, int ktb, int rowgrp, int lane) {
    const uint4* ph = (const uint4*)gh + ((rowgrp*nkt + ktb)*32 + lane);
    const uint4* pl = (const uint4*)gl + ((rowgrp*nkt + ktb)*32 + lane);
    Ah[0] = __ldcg(ph);      Ah[1] = __ldcg(ph + 32);
    Al[0] = __ldcg(pl);      Al[1] = __ldcg(pl + 32);
}

// this warp's half-chunk of MMAs (2 k-tiles); km folded into b addresses
__device__ __forceinline__ void compute_half(float X0h[4], float X0l[4], float X1h[4], float X1l[4],
    const uint4 Ah[2], const uint4 Al[2], uint32_t bh_addr, uint32_t bl_addr) {
    #pragma unroll
    for (int kk2 = 0; kk2 < 2; kk2++) {
        uint32_t bh[4], bl[4];
        ldsm4(bh, bh_addr + kk2*32);
        ldsm4(bl, bl_addr + kk2*32);
        const uint32_t* ah = (const uint32_t*)&Ah[kk2];
        const uint32_t* al = (const uint32_t*)&Al[kk2];
        mma_bf16(X0h, ah, bh[0], bh[1]);
        mma_bf16(X1h, ah, bh[2], bh[3]);
        mma_bf16(X0l, ah, bl[0], bl[1]);
        mma_bf16(X1l, ah, bl[2], bl[3]);
        mma_bf16(X0l, al, bh[0], bh[1]);
        mma_bf16(X1l, al, bh[2], bh[3]);
    }
}

__device__ __forceinline__ void gates2(const float C0[4], const float C1[4],
    float bi, float bf_, float bg, float bo, float cst[2], float hout[2]) {
    #pragma unroll
    for (int h = 0; h < 2; h++) {
        float zi = C0[2*h] + bi, zf = C0[2*h+1] + bf_;
        float zg = C1[2*h] + bg, zo = C1[2*h+1] + bo;
        float ig = 1.f/(1.f + expf(-zi));
        float fg = 1.f/(1.f + expf(-zf));
        float gg = tanhf(zg);
        float og = 1.f/(1.f + expf(-zo));
        float cn = fg*cst[h] + ig*gg;
        cst[h] = cn;
        hout[h] = og*tanhf(cn);
    }
}

__global__ void __launch_bounds__(NTHR, 1) ajrnn_kernel(
    const float* __restrict__ x,
    const float* __restrict__ k0, const float* __restrict__ r0, const float* __restrict__ b0,
    const float* __restrict__ k1, const float* __restrict__ r1, const float* __restrict__ b1,
    const float* __restrict__ Wm, const float* __restrict__ bias,
    float* __restrict__ out)
{
    extern __shared__ char smem[];
    const uint32_t smb = smem_u32(smem);
    const int tid = threadIdx.x;
    const int bid = blockIdx.x;
    const int n0  = bid * 4;
    const int dcol = bid >> 1;
    const int wid = tid >> 5, lane = tid & 31;
    float* sh_wp = (float*)(smem + SM_WP);
    float* sh_part = (float*)(smem + SM_PART);

    // ---- weights: fp32 -> bf16 hi/lo, gate-interleaved col order ----
    unsigned short* w1h = (unsigned short*)(smem + SM_W1HI);
    unsigned short* w1l = (unsigned short*)(smem + SM_W1LO);
    unsigned short* w2h = (unsigned short*)(smem + SM_W2HI);
    unsigned short* w2l = (unsigned short*)(smem + SM_W2LO);
    for (int idx = tid; idx < 16*576; idx += NTHR) {
        int p = idx & 15, k = idx >> 4;
        int col = (2*(p>>3) + (p&1))*HH + n0 + ((p&7)>>1);
        float w = (k < DD) ? k0[k*2048 + col] : r0[(k-DD)*2048 + col];
        unsigned short hb, lb; bf16split(w, hb, lb);
        w1h[p*W1_STRIDE + k] = hb;
        w1l[p*W1_STRIDE + k] = lb;
    }
    for (int idx = tid; idx < 16*1024; idx += NTHR) {
        int p = idx & 15, k = idx >> 4;
        int col = (2*(p>>3) + (p&1))*HH + n0 + ((p&7)>>1);
        float w = (k < HH) ? k1[k*2048 + col] : r1[(k-HH)*2048 + col];
        unsigned short hb, lb; bf16split(w, hb, lb);
        w2h[p*W2_STRIDE + k] = hb;
        w2l[p*W2_STRIDE + k] = lb;
    }
    sh_wp[tid] = Wm[tid*DD + dcol];
    {   // zero global state parity 0: 128 CTAs x 512 thr == BB*HH exactly
        int g = bid*NTHR + tid;
        g_h1h[0][g] = 0; g_h1l[0][g] = 0;
        g_h2h[0][g] = 0; g_h2l[0][g] = 0;
        g_h2f[0][g] = 0.f;
    }
    if (tid < 64) {
        int r = (bid & 1)*64 + tid;
        float cv = x[(r*TT)*DD + dcol];
        unsigned short chi, clo; bf16split(cv, chi, clo);
        int ci = cfrag_idx(r, dcol);
        g_curh[ci] = chi; g_curl[ci] = clo;
    }
    if (tid == 0) atomicAdd(&g_cntA, 1);
    const float biasd = bias[dcol];

    const int jj = lane & 3;
    const float bi0 = b0[0*HH + n0 + jj], bf0 = b0[1*HH + n0 + jj];
    const float bg0 = b0[2*HH + n0 + jj], bo0 = b0[3*HH + n0 + jj];
    const float bi1 = b1[0*HH + n0 + jj], bf1 = b1[1*HH + n0 + jj];
    const float bg1 = b1[2*HH + n0 + jj], bo1 = b1[3*HH + n0 + jj];

    const int rowgrp = wid & 7;                     // 8 row-groups x 16 rows
    const int km = wid >> 3;                        // k-half: warp owns kt {2km,2km+1} of each chunk
    const int km2 = 2*km;
    const int crow = rowgrp*16 + (lane >> 2);
    const int bn  = (lane & 7) | ((lane >> 1) & 8);
    const int bk8 = (lane >> 3) & 1;
    const uint32_t b1hA  = smb + SM_W1HI + bn*(W1_STRIDE*2) + bk8*16 + km*64;
    const uint32_t b1loA = smb + SM_W1LO + bn*(W1_STRIDE*2) + bk8*16 + km*64;
    const uint32_t b2hA  = smb + SM_W2HI + bn*(W2_STRIDE*2) + bk8*16 + km*64;
    const uint32_t b2loA = smb + SM_W2LO + bn*(W2_STRIDE*2) + bk8*16 + km*64;
    float* mypart = sh_part + (rowgrp*32 + lane)*8;

    grid_barrier();   // init + cur(0) visible; cntA == 128

    uint4 Ahi[2][2], Alo[2][2];          // 2-slot ring, slot = c & 1; 2 k-tiles per slot
    float c1st[2] = {0.f, 0.f}, c2st[2] = {0.f, 0.f};

    // prologue: chunks 0 (slot 0) and 1 (slot 1) of step 0 (h1old = zeros, parity 0)
    issue_half(Ahi[0], Alo[0], g_h1h[0], g_h1l[0], 32, 0*4 + km2, rowgrp, lane);
    issue_half(Ahi[1], Alo[1], g_h1h[0], g_h1l[0], 32, 1*4 + km2, rowgrp, lane);

    for (int t = 0; t < TT; t++) {
        const int rb = t & 1, wb = rb ^ 1;
        const unsigned short *h1r_h = g_h1h[rb], *h1r_l = g_h1l[rb];
        const unsigned short *h2r_h = g_h2h[rb], *h2r_l = g_h2l[rb];
        unsigned short *h1w_h = g_h1h[wb], *h1w_l = g_h1l[wb];
        unsigned short *h2w_h = g_h2h[wb], *h2w_l = g_h2l[wb];
        float B0h[4]={0,0,0,0}, B0l[4]={0,0,0,0}, B1h[4]={0,0,0,0}, B1l[4]={0,0,0,0};
        float D0h[4]={0,0,0,0}, D0l[4]={0,0,0,0}, D1h[4]={0,0,0,0}, D1l[4]={0,0,0,0};

        #pragma unroll
        for (int c = 0; c < 25; c++) {
            const int s = c & 1;
            // ---- compute half-chunk c from slot s ----
            if (c <= 7)
                compute_half(B0h,B0l,B1h,B1l, Ahi[s], Alo[s], b1hA + (64 + c*64)*2, b1loA + (64 + c*64)*2);
            else if (c <= 15)
                compute_half(D0h,D0l,D1h,D1l, Ahi[s], Alo[s], b2hA + (512 + (c-8)*64)*2, b2loA + (512 + (c-8)*64)*2);
            else if (c == 16)
                compute_half(B0h,B0l,B1h,B1l, Ahi[s], Alo[s], b1hA, b1loA);
            else
                compute_half(D0h,D0l,D1h,D1l, Ahi[s], Alo[s], b2hA + ((c-17)*64)*2, b2loA + ((c-17)*64)*2);

            // ---- gates + issue (target slot s, just freed) ----
            if (c <= 5) {
                issue_half(Ahi[s], Alo[s], h1r_h, h1r_l, 32, (c+2)*4 + km2, rowgrp, lane);
            } else if (c <= 13) {
                if (c == 6) poll_cnt(&g_cntC, 128*t);
                issue_half(Ahi[s], Alo[s], h2r_h, h2r_l, 32, (c+2-8)*4 + km2, rowgrp, lane);
                if (c == 13 && t > 0) {
                    // Phase A(t): pred + impute cur(t) (h2f(t-1) gated by cntC at c==6)
                    const int r  = (bid & 1)*64 + (tid >> 3);
                    const int l8 = tid & 7;
                    const float* hrow = &g_h2f[rb][r*HH + l8*64];
                    const float* wv = sh_wp + l8*64;
                    float sacc = 0.f;
                    #pragma unroll
                    for (int kk = 0; kk < 64; kk += 4) {
                        float4 h4 = __ldcg((const float4*)(hrow + kk));
                        sacc += h4.x*wv[kk] + h4.y*wv[kk+1] + h4.z*wv[kk+2] + h4.w*wv[kk+3];
                    }
                    sacc += __shfl_xor_sync(0xffffffffu, sacc, 4);
                    sacc += __shfl_xor_sync(0xffffffffu, sacc, 2);
                    sacc += __shfl_xor_sync(0xffffffffu, sacc, 1);
                    if (l8 == 0) {
                        float p  = sacc + biasd;
                        float xv = x[(r*TT + t)*DD + dcol];
                        float cv = (xv == 128.0f) ? p : xv;
                        unsigned short chi, clo; bf16split(cv, chi, clo);
                        int ci = cfrag_idx(r, dcol);
                        g_curh[ci] = chi; g_curl[ci] = clo;
                        out[(r*(TT-1) + (t-1))*DD + dcol] = p;
                    }
                    __syncthreads();
                    if (tid == 0) { __threadfence(); atomicAdd(&g_cntA, 1); }
                }
            } else if (c == 14) {
                poll_cnt(&g_cntA, 128*(t+1));
                issue_half(Ahi[0], Alo[0], g_curh, g_curl, 4, km2, rowgrp, lane);  // chunk 16 -> slot 0
            } else if (c == 16) {
                // ---- B epilogue: combine k-halves, h1(t) ----
                float C0[4], C1[4];
                #pragma unroll
                for (int q = 0; q < 4; q++) { C0[q] = B0h[q] + B0l[q]; C1[q] = B1h[q] + B1l[q]; }
                if (km == 1) {
                    #pragma unroll
                    for (int q = 0; q < 4; q++) { mypart[q] = C0[q]; mypart[4+q] = C1[q]; }
                }
                __syncthreads();
                if (km == 0) {
                    #pragma unroll
                    for (int q = 0; q < 4; q++) { C0[q] += mypart[q]; C1[q] += mypart[4+q]; }
                    float hout[2];
                    gates2(C0, C1, bi0, bf0, bg0, bo0, c1st, hout);
                    #pragma unroll
                    for (int h = 0; h < 2; h++) {
                        int r = crow + 8*h;
                        unsigned short hi, lo; bf16split(hout[h], hi, lo);
                        int p = hfrag_idx(r, n0 + jj);
                        h1w_h[p] = hi; h1w_l[p] = lo;
                    }
                }
                __syncthreads();
                if (tid == 0) { __threadfence(); atomicAdd(&g_cntB, 1); }
                poll_cnt(&g_cntB, 128*(t+1));
                issue_half(Ahi[1], Alo[1], h1w_h, h1w_l, 32, 0*4 + km2, rowgrp, lane); // 17 -> slot 1
                issue_half(Ahi[0], Alo[0], h1w_h, h1w_l, 32, 1*4 + km2, rowgrp, lane); // 18 -> slot 0
            } else if (c >= 17 && c <= 22) {
                issue_half(Ahi[s], Alo[s], h1w_h, h1w_l, 32, (c+2-17)*4 + km2, rowgrp, lane);
            } else if (c == 24) {
                if (t + 1 < TT) {
                    issue_half(Ahi[0], Alo[0], h1w_h, h1w_l, 32, 0*4 + km2, rowgrp, lane);
                    issue_half(Ahi[1], Alo[1], h1w_h, h1w_l, 32, 1*4 + km2, rowgrp, lane);
                }
            }
            // c == 15, 23: no issue
        }

        // ---- C epilogue: combine k-halves, h2(t) ----
        {
            float C0[4], C1[4];
            #pragma unroll
            for (int q = 0; q < 4; q++) { C0[q] = D0h[q] + D0l[q]; C1[q] = D1h[q] + D1l[q]; }
            if (km == 1) {
                #pragma unroll
                for (int q = 0; q < 4; q++) { mypart[q] = C0[q]; mypart[4+q] = C1[q]; }
            }
            __syncthreads();
            if (km == 0) {
                #pragma unroll
                for (int q = 0; q < 4; q++) { C0[q] += mypart[q]; C1[q] += mypart[4+q]; }
                float hout[2];
                gates2(C0, C1, bi1, bf1, bg1, bo1, c2st, hout);
                #pragma unroll
                for (int h = 0; h < 2; h++) {
                    int r = crow + 8*h;
                    unsigned short hi, lo; bf16split(hout[h], hi, lo);
                    int p = hfrag_idx(r, n0 + jj);
                    h2w_h[p] = hi; h2w_l[p] = lo;
                    g_h2f[wb][r*HH + n0 + jj] = hout[h];
                    if (t == TT-1) out[PRED_SZ + r*HH + n0 + jj] = hout[h];
                }
            }
            __syncthreads();
            if (tid == 0) { __threadfence(); atomicAdd(&g_cntC, 1); }
        }
    }

    grid_barrier();
    if (bid == 0 && tid == 0) { g_cntA = 0; g_cntB = 0; g_cntC = 0; }
}

extern "C" void kernel_launch(void* const* d_in, const int* in_sizes, int n_in,
                              void* d_out, int out_size) {
    (void)in_sizes; (void)n_in; (void)out_size;
    const float* x    = (const float*)d_in[0];
    const float* k0   = (const float*)d_in[1];
    const float* r0   = (const float*)d_in[2];
    const float* b0   = (const float*)d_in[3];
    const float* k1   = (const float*)d_in[4];
    const float* r1   = (const float*)d_in[5];
    const float* b1   = (const float*)d_in[6];
    const float* Wm   = (const float*)d_in[7];
    const float* bias = (const float*)d_in[8];
    cudaFuncSetAttribute(ajrnn_kernel, cudaFuncAttributeMaxDynamicSharedMemorySize, SM_TOTAL);
    ajrnn_kernel<<<NBLK, NTHR, SM_TOTAL>>>(x, k0, r0, b0, k1, r1, b1, Wm, bias, (float*)d_out);
}

// round 16
// speedup vs baseline: 1.2750x; 1.2750x over previous
#include <cuda_runtime.h>
#include <cuda_bf16.h>
#include <cstdint>

#define BB 128
#define TT 256
#define DD 64
#define HH 512
#define NBLK 128
#define NTHR 256
#define PRED_SZ (BB*(TT-1)*DD)

// smem: weights only (bf16 hi/lo) + Wm column
#define W1_STRIDE 584
#define W2_STRIDE 1032
#define SM_W1HI 0
#define SM_W1LO (SM_W1HI + 16*W1_STRIDE*2)
#define SM_W2HI (SM_W1LO + 16*W1_STRIDE*2)
#define SM_W2LO (SM_W2HI + 16*W2_STRIDE*2)
#define SM_WP   (SM_W2LO + 16*W2_STRIDE*2)
#define SM_TOTAL (SM_WP + 2048)

// h state in GLOBAL MEMORY in mma-fragment layout.
__device__ __align__(16) unsigned short g_h1h[2][BB*HH], g_h1l[2][BB*HH];
__device__ __align__(16) unsigned short g_h2h[2][BB*HH], g_h2l[2][BB*HH];
__device__ __align__(16) float g_h2f[2][BB*HH];
__device__ __align__(16) unsigned short g_curh[BB*DD], g_curl[BB*DD];
__device__ unsigned int g_bar;
__device__ int g_cntA, g_cntB, g_cntC;   // reset to 0 at end of every launch

__device__ __forceinline__ uint32_t smem_u32(const void* p) {
    uint32_t a;
    asm("{ .reg .u64 t; cvta.to.shared.u64 t, %1; cvt.u32.u64 %0, t; }" : "=r"(a) : "l"(p));
    return a;
}
__device__ __forceinline__ void ldsm4(uint32_t r[4], uint32_t addr) {
    asm volatile("ldmatrix.sync.aligned.m8n8.x4.shared.b16 {%0,%1,%2,%3}, [%4];"
        : "=r"(r[0]), "=r"(r[1]), "=r"(r[2]), "=r"(r[3]) : "r"(addr));
}
__device__ __forceinline__ void mma_bf16(float c[4], const uint32_t a[4], uint32_t b0, uint32_t b1) {
    asm volatile("mma.sync.aligned.m16n8k16.row.col.f32.bf16.bf16.f32 "
        "{%0,%1,%2,%3}, {%4,%5,%6,%7}, {%8,%9}, {%0,%1,%2,%3};"
        : "+f"(c[0]), "+f"(c[1]), "+f"(c[2]), "+f"(c[3])
        : "r"(a[0]), "r"(a[1]), "r"(a[2]), "r"(a[3]), "r"(b0), "r"(b1));
}
__device__ __forceinline__ void bf16split(float v, unsigned short &hi, unsigned short &lo) {
    __nv_bfloat16 hb = __float2bfloat16(v);
    hi = __bfloat16_as_ushort(hb);
    lo = __bfloat16_as_ushort(__float2bfloat16(v - __bfloat162float(hb)));
}
__device__ __forceinline__ int hfrag_idx(int r, int c) {
    int rb = r >> 4, kt = c >> 4;
    int l = ((r & 7) << 2) | ((c >> 1) & 3);
    int j = ((r >> 3) & 1) | (((c >> 3) & 1) << 1);
    return (((rb*32 + kt)*32 + l) << 3) + j*2 + (c & 1);
}
__device__ __forceinline__ int cfrag_idx(int r, int c) {
    int rb = r >> 4, kt = c >> 4;
    int l = ((r & 7) << 2) | ((c >> 1) & 3);
    int j = ((r >> 3) & 1) | (((c >> 3) & 1) << 1);
    return (((rb*4 + kt)*32 + l) << 3) + j*2 + (c & 1);
}

__device__ __forceinline__ void grid_barrier() {
    __syncthreads();
    if (threadIdx.x == 0) {
        __threadfence();
        unsigned my = atomicAdd(&g_bar, 1u) + 1u;
        unsigned target = my + (NBLK - 1u) - ((my - 1u) % NBLK);
        while ((int)(*(volatile unsigned*)&g_bar - target) < 0) __nanosleep(32);
        __threadfence();
    }
    __syncthreads();
}

__device__ __forceinline__ void poll_cnt(int* cnt, int target) {
    if ((threadIdx.x & 31) == 0) {
        volatile int* c = (volatile int*)cnt;
        while (*c < target) __nanosleep(32);
    }
    __syncwarp();
    __threadfence();
}

// load one 64-k chunk of A fragments (hi+lo) into registers via LDG.128.cg
__device__ __forceinline__ void issue_chunk(uint4 Ah[4], uint4 Al[4],
    const unsigned short* __restrict__ gh, const unsigned short* __restrict__ gl,
    int nkt, int ktb, int rowgrp, int lane) {
    const uint4* ph = (const uint4*)gh + ((rowgrp*nkt + ktb)*32 + lane);
    const uint4* pl = (const uint4*)gl + ((rowgrp*nkt + ktb)*32 + lane);
    #pragma unroll
    for (int i = 0; i < 4; i++) { Ah[i] = __ldcg(ph + i*32); Al[i] = __ldcg(pl + i*32); }
}

__device__ __forceinline__ void compute_chunk(float X0h[4], float X0l[4], float X1h[4], float X1l[4],
    const uint4 Ah[4], const uint4 Al[4], uint32_t bh_addr, uint32_t bl_addr) {
    #pragma unroll
    for (int kk = 0; kk < 4; kk++) {
        uint32_t bh[4], bl[4];
        ldsm4(bh, bh_addr + kk*32);
        ldsm4(bl, bl_addr + kk*32);
        const uint32_t* ah = (const uint32_t*)&Ah[kk];
        const uint32_t* al = (const uint32_t*)&Al[kk];
        mma_bf16(X0h, ah, bh[0], bh[1]);
        mma_bf16(X1h, ah, bh[2], bh[3]);
        mma_bf16(X0l, ah, bl[0], bl[1]);
        mma_bf16(X1l, ah, bl[2], bl[3]);
        mma_bf16(X0l, al, bh[0], bh[1]);
        mma_bf16(X1l, al, bh[2], bh[3]);
    }
}

__device__ __forceinline__ void gates2(const float C0[4], const float C1[4],
    float bi, float bf_, float bg, float bo, float cst[2], float hout[2]) {
    #pragma unroll
    for (int h = 0; h < 2; h++) {
        float zi = C0[2*h] + bi, zf = C0[2*h+1] + bf_;
        float zg = C1[2*h] + bg, zo = C1[2*h+1] + bo;
        float ig = 1.f/(1.f + expf(-zi));
        float fg = 1.f/(1.f + expf(-zf));
        float gg = tanhf(zg);
        float og = 1.f/(1.f + expf(-zo));
        float cn = fg*cst[h] + ig*gg;
        cst[h] = cn;
        hout[h] = og*tanhf(cn);
    }
}

__global__ void __launch_bounds__(NTHR, 1) ajrnn_kernel(
    const float* __restrict__ x,
    const float* __restrict__ k0, const float* __restrict__ r0, const float* __restrict__ b0,
    const float* __restrict__ k1, const float* __restrict__ r1, const float* __restrict__ b1,
    const float* __restrict__ Wm, const float* __restrict__ bias,
    float* __restrict__ out)
{
    extern __shared__ char smem[];
    const uint32_t smb = smem_u32(smem);
    const int tid = threadIdx.x;
    const int bid = blockIdx.x;
    const int n0  = bid * 4;
    const int dcol = bid >> 1;
    const int wid = tid >> 5, lane = tid & 31;
    float* sh_wp = (float*)(smem + SM_WP);

    // ---- weights: fp32 -> bf16 hi/lo, gate-interleaved col order ----
    unsigned short* w1h = (unsigned short*)(smem + SM_W1HI);
    unsigned short* w1l = (unsigned short*)(smem + SM_W1LO);
    unsigned short* w2h = (unsigned short*)(smem + SM_W2HI);
    unsigned short* w2l = (unsigned short*)(smem + SM_W2LO);
    for (int idx = tid; idx < 16*576; idx += NTHR) {
        int p = idx & 15, k = idx >> 4;
        int col = (2*(p>>3) + (p&1))*HH + n0 + ((p&7)>>1);
        float w = (k < DD) ? k0[k*2048 + col] : r0[(k-DD)*2048 + col];
        unsigned short hb, lb; bf16split(w, hb, lb);
        w1h[p*W1_STRIDE + k] = hb;
        w1l[p*W1_STRIDE + k] = lb;
    }
    for (int idx = tid; idx < 16*1024; idx += NTHR) {
        int p = idx & 15, k = idx >> 4;
        int col = (2*(p>>3) + (p&1))*HH + n0 + ((p&7)>>1);
        float w = (k < HH) ? k1[k*2048 + col] : r1[(k-HH)*2048 + col];
        unsigned short hb, lb; bf16split(w, hb, lb);
        w2h[p*W2_STRIDE + k] = hb;
        w2l[p*W2_STRIDE + k] = lb;
    }
    for (int i = tid; i < 512; i += NTHR) sh_wp[i] = Wm[i*DD + dcol];
    #pragma unroll
    for (int i = 0; i < 2; i++) {
        int g = i*(NBLK*NTHR) + bid*NTHR + tid;
        g_h1h[0][g] = 0; g_h1l[0][g] = 0;
        g_h2h[0][g] = 0; g_h2l[0][g] = 0;
        g_h2f[0][g] = 0.f;
    }
    if (tid < 64) {
        int r = (bid & 1)*64 + tid;
        float cv = x[(r*TT)*DD + dcol];
        unsigned short chi, clo; bf16split(cv, chi, clo);
        int ci = cfrag_idx(r, dcol);
        g_curh[ci] = chi; g_curl[ci] = clo;
    }
    if (tid == 0) atomicAdd(&g_cntA, 1);
    const float biasd = bias[dcol];

    const int jj = lane & 3;
    const float bi0 = b0[0*HH + n0 + jj], bf0 = b0[1*HH + n0 + jj];
    const float bg0 = b0[2*HH + n0 + jj], bo0 = b0[3*HH + n0 + jj];
    const float bi1 = b1[0*HH + n0 + jj], bf1 = b1[1*HH + n0 + jj];
    const float bg1 = b1[2*HH + n0 + jj], bo1 = b1[3*HH + n0 + jj];

    const int rowgrp = wid;
    const int crow = rowgrp*16 + (lane >> 2);
    const int bn  = (lane & 7) | ((lane >> 1) & 8);
    const int bk8 = (lane >> 3) & 1;
    const uint32_t b1hA  = smb + SM_W1HI + bn*(W1_STRIDE*2) + bk8*16;
    const uint32_t b1loA = smb + SM_W1LO + bn*(W1_STRIDE*2) + bk8*16;
    const uint32_t b2hA  = smb + SM_W2HI + bn*(W2_STRIDE*2) + bk8*16;
    const uint32_t b2loA = smb + SM_W2LO + bn*(W2_STRIDE*2) + bk8*16;

    grid_barrier();   // init + cur(0) visible; cntA == 128

    uint4 Ahi[2][4], Alo[2][4];          // 2-slot ring, slot = c & 1
    float c1st[2] = {0.f, 0.f}, c2st[2] = {0.f, 0.f};

    // prologue: chunks 0 (slot 0) and 1 (slot 1) of step 0 (h1old = zeros, parity 0)
    issue_chunk(Ahi[0], Alo[0], g_h1h[0], g_h1l[0], 32, 0, rowgrp, lane);
    issue_chunk(Ahi[1], Alo[1], g_h1h[0], g_h1l[0], 32, 4, rowgrp, lane);

    for (int t = 0; t < TT; t++) {
        const int rb = t & 1, wb = rb ^ 1;
        const unsigned short *h1r_h = g_h1h[rb], *h1r_l = g_h1l[rb];
        const unsigned short *h2r_h = g_h2h[rb], *h2r_l = g_h2l[rb];
        unsigned short *h1w_h = g_h1h[wb], *h1w_l = g_h1l[wb];
        unsigned short *h2w_h = g_h2h[wb], *h2w_l = g_h2l[wb];
        float B0h[4]={0,0,0,0}, B0l[4]={0,0,0,0}, B1h[4]={0,0,0,0}, B1l[4]={0,0,0,0};
        float D0h[4]={0,0,0,0}, D0l[4]={0,0,0,0}, D1h[4]={0,0,0,0}, D1l[4]={0,0,0,0};

        #pragma unroll
        for (int c = 0; c < 25; c++) {
            const int s = c & 1;
            // ---- compute chunk c from slot s ----
            if (c <= 7)
                compute_chunk(B0h,B0l,B1h,B1l, Ahi[s], Alo[s], b1hA + (64 + c*64)*2, b1loA + (64 + c*64)*2);
            else if (c <= 15)
                compute_chunk(D0h,D0l,D1h,D1l, Ahi[s], Alo[s], b2hA + (512 + (c-8)*64)*2, b2loA + (512 + (c-8)*64)*2);
            else if (c == 16)
                compute_chunk(B0h,B0l,B1h,B1l, Ahi[s], Alo[s], b1hA, b1loA);
            else
                compute_chunk(D0h,D0l,D1h,D1l, Ahi[s], Alo[s], b2hA + ((c-17)*64)*2, b2loA + ((c-17)*64)*2);

            // ---- gates + issue (target slot s, just freed by this compute) ----
            if (c <= 5) {
                issue_chunk(Ahi[s], Alo[s], h1r_h, h1r_l, 32, (c+2)*4, rowgrp, lane);
            } else if (c <= 13) {
                if (c == 6) poll_cnt(&g_cntC, 128*t);
                issue_chunk(Ahi[s], Alo[s], h2r_h, h2r_l, 32, (c+2-8)*4, rowgrp, lane);
                if (c == 13 && t > 0) {
                    // Phase A(t): pred + impute cur(t) (h2f(t-1) gated by cntC at c==6)
                    // unroll capped at 4 to bound the register transient (spill fix)
                    const int r  = (bid & 1)*64 + (tid >> 2);
                    const int l4 = tid & 3;
                    const float* hrow = &g_h2f[rb][r*HH + l4*128];
                    const float* wv = sh_wp + l4*128;
                    float sacc0 = 0.f, sacc1 = 0.f;
                    #pragma unroll 4
                    for (int kk = 0; kk < 128; kk += 8) {
                        float4 ha = __ldcg((const float4*)(hrow + kk));
                        float4 hb = __ldcg((const float4*)(hrow + kk + 4));
                        sacc0 += ha.x*wv[kk]   + ha.y*wv[kk+1] + ha.z*wv[kk+2] + ha.w*wv[kk+3];
                        sacc1 += hb.x*wv[kk+4] + hb.y*wv[kk+5] + hb.z*wv[kk+6] + hb.w*wv[kk+7];
                    }
                    float sacc = sacc0 + sacc1;
                    sacc += __shfl_xor_sync(0xffffffffu, sacc, 2);
                    sacc += __shfl_xor_sync(0xffffffffu, sacc, 1);
                    if (l4 == 0) {
                        float p  = sacc + biasd;
                        float xv = x[(r*TT + t)*DD + dcol];
                        float cv = (xv == 128.0f) ? p : xv;
                        unsigned short chi, clo; bf16split(cv, chi, clo);
                        int ci = cfrag_idx(r, dcol);
                        g_curh[ci] = chi; g_curl[ci] = clo;
                        out[(r*(TT-1) + (t-1))*DD + dcol] = p;
                    }
                    __syncthreads();
                    if (tid == 0) { __threadfence(); atomicAdd(&g_cntA, 1); }
                }
            } else if (c == 14) {
                poll_cnt(&g_cntA, 128*(t+1));
                issue_chunk(Ahi[0], Alo[0], g_curh, g_curl, 4, 0, rowgrp, lane);   // chunk 16 -> slot 0
            } else if (c == 16) {
                // ---- B epilogue: h1(t) ----
                float C0[4], C1[4];
                #pragma unroll
                for (int q = 0; q < 4; q++) { C0[q] = B0h[q] + B0l[q]; C1[q] = B1h[q] + B1l[q]; }
                float hout[2];
                gates2(C0, C1, bi0, bf0, bg0, bo0, c1st, hout);
                #pragma unroll
                for (int h = 0; h < 2; h++) {
                    int r = crow + 8*h;
                    unsigned short hi, lo; bf16split(hout[h], hi, lo);
                    int p = hfrag_idx(r, n0 + jj);
                    h1w_h[p] = hi; h1w_l[p] = lo;
                }
                __syncthreads();
                if (tid == 0) { __threadfence(); atomicAdd(&g_cntB, 1); }
                poll_cnt(&g_cntB, 128*(t+1));
                issue_chunk(Ahi[1], Alo[1], h1w_h, h1w_l, 32, 0*4, rowgrp, lane); // 17 -> slot 1
                issue_chunk(Ahi[0], Alo[0], h1w_h, h1w_l, 32, 1*4, rowgrp, lane); // 18 -> slot 0
            } else if (c >= 17 && c <= 22) {
                issue_chunk(Ahi[s], Alo[s], h1w_h, h1w_l, 32, (c+2-17)*4, rowgrp, lane);
            } else if (c == 24) {
                if (t + 1 < TT) {
                    issue_chunk(Ahi[0], Alo[0], h1w_h, h1w_l, 32, 0*4, rowgrp, lane);
                    issue_chunk(Ahi[1], Alo[1], h1w_h, h1w_l, 32, 1*4, rowgrp, lane);
                }
            }
            // c == 15, 23: no issue
        }

        // ---- C epilogue: h2(t) ----
        {
            float C0[4], C1[4];
            #pragma unroll
            for (int q = 0; q < 4; q++) { C0[q] = D0h[q] + D0l[q]; C1[q] = D1h[q] + D1l[q]; }
            float hout[2];
            gates2(C0, C1, bi1, bf1, bg1, bo1, c2st, hout);
            #pragma unroll
            for (int h = 0; h < 2; h++) {
                int r = crow + 8*h;
                unsigned short hi, lo; bf16split(hout[h], hi, lo);
                int p = hfrag_idx(r, n0 + jj);
                h2w_h[p] = hi; h2w_l[p] = lo;
                g_h2f[wb][r*HH + n0 + jj] = hout[h];
                if (t == TT-1) out[PRED_SZ + r*HH + n0 + jj] = hout[h];
            }
            __syncthreads();
            if (tid == 0) { __threadfence(); atomicAdd(&g_cntC, 1); }
        }
    }

    grid_barrier();
    if (bid == 0 && tid == 0) { g_cntA = 0; g_cntB = 0; g_cntC = 0; }
}

extern "C" void kernel_launch(void* const* d_in, const int* in_sizes, int n_in,
                              void* d_out, int out_size) {
    (void)in_sizes; (void)n_in; (void)out_size;
    const float* x    = (const float*)d_in[0];
    const float* k0   = (const float*)d_in[1];
    const float* r0   = (const float*)d_in[2];
    const float* b0   = (const float*)d_in[3];
    const float* k1   = (const float*)d_in[4];
    const float* r1   = (const float*)d_in[5];
    const float* b1   = (const float*)d_in[6];
    const float* Wm   = (const float*)d_in[7];
    const float* bias = (const float*)d_in[8];
    cudaFuncSetAttribute(ajrnn_kernel, cudaFuncAttributeMaxDynamicSharedMemorySize, SM_TOTAL);
    ajrnn_kernel<<<NBLK, NTHR, SM_TOTAL>>>(x, k0, r0, b0, k1, r1, b1, Wm, bias, (float*)d_out);
}

// round 17
// speedup vs baseline: 1.4516x; 1.1385x over previous
#include <cuda_runtime.h>
#include <cuda_bf16.h>
#include <cstdint>

#define BB 128
#define TT 256
#define DD 64
#define HH 512
#define NBLK 128
#define NTHR 256
#define PRED_SZ (BB*(TT-1)*DD)

// smem: weights only (bf16 hi/lo) + Wm column
#define W1_STRIDE 584
#define W2_STRIDE 1032
#define SM_W1HI 0
#define SM_W1LO (SM_W1HI + 16*W1_STRIDE*2)
#define SM_W2HI (SM_W1LO + 16*W1_STRIDE*2)
#define SM_W2LO (SM_W2HI + 16*W2_STRIDE*2)
#define SM_WP   (SM_W2LO + 16*W2_STRIDE*2)
#define SM_TOTAL (SM_WP + 2048)

// h state in GLOBAL MEMORY in mma-fragment layout.
__device__ __align__(16) unsigned short g_h1h[2][BB*HH], g_h1l[2][BB*HH];
__device__ __align__(16) unsigned short g_h2h[2][BB*HH], g_h2l[2][BB*HH];
__device__ __align__(16) float g_h2f[2][BB*HH];
__device__ __align__(16) unsigned short g_curh[BB*DD], g_curl[BB*DD];
__device__ unsigned int g_bar;
__device__ int g_cntA, g_cntB, g_cntC;   // reset to 0 at end of every launch

__device__ __forceinline__ uint32_t smem_u32(const void* p) {
    uint32_t a;
    asm("{ .reg .u64 t; cvta.to.shared.u64 t, %1; cvt.u32.u64 %0, t; }" : "=r"(a) : "l"(p));
    return a;
}
__device__ __forceinline__ void ldsm4(uint32_t r[4], uint32_t addr) {
    asm volatile("ldmatrix.sync.aligned.m8n8.x4.shared.b16 {%0,%1,%2,%3}, [%4];"
        : "=r"(r[0]), "=r"(r[1]), "=r"(r[2]), "=r"(r[3]) : "r"(addr));
}
__device__ __forceinline__ void mma_bf16(float c[4], const uint32_t a[4], uint32_t b0, uint32_t b1) {
    asm volatile("mma.sync.aligned.m16n8k16.row.col.f32.bf16.bf16.f32 "
        "{%0,%1,%2,%3}, {%4,%5,%6,%7}, {%8,%9}, {%0,%1,%2,%3};"
        : "+f"(c[0]), "+f"(c[1]), "+f"(c[2]), "+f"(c[3])
        : "r"(a[0]), "r"(a[1]), "r"(a[2]), "r"(a[3]), "r"(b0), "r"(b1));
}
__device__ __forceinline__ void bf16split(float v, unsigned short &hi, unsigned short &lo) {
    __nv_bfloat16 hb = __float2bfloat16(v);
    hi = __bfloat16_as_ushort(hb);
    lo = __bfloat16_as_ushort(__float2bfloat16(v - __bfloat162float(hb)));
}
__device__ __forceinline__ int hfrag_idx(int r, int c) {
    int rb = r >> 4, kt = c >> 4;
    int l = ((r & 7) << 2) | ((c >> 1) & 3);
    int j = ((r >> 3) & 1) | (((c >> 3) & 1) << 1);
    return (((rb*32 + kt)*32 + l) << 3) + j*2 + (c & 1);
}
__device__ __forceinline__ int cfrag_idx(int r, int c) {
    int rb = r >> 4, kt = c >> 4;
    int l = ((r & 7) << 2) | ((c >> 1) & 3);
    int j = ((r >> 3) & 1) | (((c >> 3) & 1) << 1);
    return (((rb*4 + kt)*32 + l) << 3) + j*2 + (c & 1);
}

__device__ __forceinline__ void grid_barrier() {
    __syncthreads();
    if (threadIdx.x == 0) {
        __threadfence();
        unsigned my = atomicAdd(&g_bar, 1u) + 1u;
        unsigned target = my + (NBLK - 1u) - ((my - 1u) % NBLK);
        while ((int)(*(volatile unsigned*)&g_bar - target) < 0) __nanosleep(32);
        __threadfence();
    }
    __syncthreads();
}

__device__ __forceinline__ void poll_cnt(int* cnt, int target) {
    if ((threadIdx.x & 31) == 0) {
        volatile int* c = (volatile int*)cnt;
        while (*c < target) __nanosleep(32);
    }
    __syncwarp();
    __threadfence();
}

// load one 64-k chunk of A fragments (hi+lo) into registers via LDG.128.cg
__device__ __forceinline__ void issue_chunk(uint4 Ah[4], uint4 Al[4],
    const unsigned short* __restrict__ gh, const unsigned short* __restrict__ gl,
    int nkt, int ktb, int rowgrp, int lane) {
    const uint4* ph = (const uint4*)gh + ((rowgrp*nkt + ktb)*32 + lane);
    const uint4* pl = (const uint4*)gl + ((rowgrp*nkt + ktb)*32 + lane);
    #pragma unroll
    for (int i = 0; i < 4; i++) { Ah[i] = __ldcg(ph + i*32); Al[i] = __ldcg(pl + i*32); }
}

__device__ __forceinline__ void compute_chunk(float X0h[4], float X0l[4], float X1h[4], float X1l[4],
    const uint4 Ah[4], const uint4 Al[4], uint32_t bh_addr, uint32_t bl_addr) {
    #pragma unroll
    for (int kk = 0; kk < 4; kk++) {
        uint32_t bh[4], bl[4];
        ldsm4(bh, bh_addr + kk*32);
        ldsm4(bl, bl_addr + kk*32);
        const uint32_t* ah = (const uint32_t*)&Ah[kk];
        const uint32_t* al = (const uint32_t*)&Al[kk];
        mma_bf16(X0h, ah, bh[0], bh[1]);
        mma_bf16(X1h, ah, bh[2], bh[3]);
        mma_bf16(X0l, ah, bl[0], bl[1]);
        mma_bf16(X1l, ah, bl[2], bl[3]);
        mma_bf16(X0l, al, bh[0], bh[1]);
        mma_bf16(X1l, al, bh[2], bh[3]);
    }
}

__device__ __forceinline__ void gates2(const float C0[4], const float C1[4],
    float bi, float bf_, float bg, float bo, float cst[2], float hout[2]) {
    #pragma unroll
    for (int h = 0; h < 2; h++) {
        float zi = C0[2*h] + bi, zf = C0[2*h+1] + bf_;
        float zg = C1[2*h] + bg, zo = C1[2*h+1] + bo;
        float ig = 1.f/(1.f + expf(-zi));
        float fg = 1.f/(1.f + expf(-zf));
        float gg = tanhf(zg);
        float og = 1.f/(1.f + expf(-zo));
        float cn = fg*cst[h] + ig*gg;
        cst[h] = cn;
        hout[h] = og*tanhf(cn);
    }
}

__global__ void __launch_bounds__(NTHR, 1) ajrnn_kernel(
    const float* __restrict__ x,
    const float* __restrict__ k0, const float* __restrict__ r0, const float* __restrict__ b0,
    const float* __restrict__ k1, const float* __restrict__ r1, const float* __restrict__ b1,
    const float* __restrict__ Wm, const float* __restrict__ bias,
    float* __restrict__ out)
{
    extern __shared__ char smem[];
    const uint32_t smb = smem_u32(smem);
    const int tid = threadIdx.x;
    const int bid = blockIdx.x;
    const int n0  = bid * 4;
    const int dcol = bid >> 1;
    const int wid = tid >> 5, lane = tid & 31;
    float* sh_wp = (float*)(smem + SM_WP);

    // ---- weights: fp32 -> bf16 hi/lo, gate-interleaved col order ----
    unsigned short* w1h = (unsigned short*)(smem + SM_W1HI);
    unsigned short* w1l = (unsigned short*)(smem + SM_W1LO);
    unsigned short* w2h = (unsigned short*)(smem + SM_W2HI);
    unsigned short* w2l = (unsigned short*)(smem + SM_W2LO);
    for (int idx = tid; idx < 16*576; idx += NTHR) {
        int p = idx & 15, k = idx >> 4;
        int col = (2*(p>>3) + (p&1))*HH + n0 + ((p&7)>>1);
        float w = (k < DD) ? k0[k*2048 + col] : r0[(k-DD)*2048 + col];
        unsigned short hb, lb; bf16split(w, hb, lb);
        w1h[p*W1_STRIDE + k] = hb;
        w1l[p*W1_STRIDE + k] = lb;
    }
    for (int idx = tid; idx < 16*1024; idx += NTHR) {
        int p = idx & 15, k = idx >> 4;
        int col = (2*(p>>3) + (p&1))*HH + n0 + ((p&7)>>1);
        float w = (k < HH) ? k1[k*2048 + col] : r1[(k-HH)*2048 + col];
        unsigned short hb, lb; bf16split(w, hb, lb);
        w2h[p*W2_STRIDE + k] = hb;
        w2l[p*W2_STRIDE + k] = lb;
    }
    for (int i = tid; i < 512; i += NTHR) sh_wp[i] = Wm[i*DD + dcol];
    #pragma unroll
    for (int i = 0; i < 2; i++) {
        int g = i*(NBLK*NTHR) + bid*NTHR + tid;
        g_h1h[0][g] = 0; g_h1l[0][g] = 0;
        g_h2h[0][g] = 0; g_h2l[0][g] = 0;
        g_h2f[0][g] = 0.f;
    }
    if (tid < 64) {
        int r = (bid & 1)*64 + tid;
        float cv = x[(r*TT)*DD + dcol];
        unsigned short chi, clo; bf16split(cv, chi, clo);
        int ci = cfrag_idx(r, dcol);
        g_curh[ci] = chi; g_curl[ci] = clo;
    }
    if (tid == 0) atomicAdd(&g_cntA, 1);
    const float biasd = bias[dcol];

    const int jj = lane & 3;
    const float bi0 = b0[0*HH + n0 + jj], bf0 = b0[1*HH + n0 + jj];
    const float bg0 = b0[2*HH + n0 + jj], bo0 = b0[3*HH + n0 + jj];
    const float bi1 = b1[0*HH + n0 + jj], bf1 = b1[1*HH + n0 + jj];
    const float bg1 = b1[2*HH + n0 + jj], bo1 = b1[3*HH + n0 + jj];

    const int rowgrp = wid;
    const int crow = rowgrp*16 + (lane >> 2);
    const int bn  = (lane & 7) | ((lane >> 1) & 8);
    const int bk8 = (lane >> 3) & 1;
    const uint32_t b1hA  = smb + SM_W1HI + bn*(W1_STRIDE*2) + bk8*16;
    const uint32_t b1loA = smb + SM_W1LO + bn*(W1_STRIDE*2) + bk8*16;
    const uint32_t b2hA  = smb + SM_W2HI + bn*(W2_STRIDE*2) + bk8*16;
    const uint32_t b2loA = smb + SM_W2LO + bn*(W2_STRIDE*2) + bk8*16;

    grid_barrier();   // init + cur(0) visible; cntA == 128

    uint4 Ahi[2][4], Alo[2][4];          // 2-slot ring, slot = c & 1
    float c1st[2] = {0.f, 0.f}, c2st[2] = {0.f, 0.f};

    // prologue: chunks 0 (slot 0) and 1 (slot 1) of step 0 (h1old = zeros, parity 0)
    issue_chunk(Ahi[0], Alo[0], g_h1h[0], g_h1l[0], 32, 0, rowgrp, lane);
    issue_chunk(Ahi[1], Alo[1], g_h1h[0], g_h1l[0], 32, 4, rowgrp, lane);

    // Stream per step: [c0-7: W1 h1old] [c8: W1 cur + B-epi] [c9-16: W2 h2old] [c17-24: W2 h1new]
    for (int t = 0; t < TT; t++) {
        const int rb = t & 1, wb = rb ^ 1;
        const unsigned short *h1r_h = g_h1h[rb], *h1r_l = g_h1l[rb];
        const unsigned short *h2r_h = g_h2h[rb], *h2r_l = g_h2l[rb];
        unsigned short *h1w_h = g_h1h[wb], *h1w_l = g_h1l[wb];
        unsigned short *h2w_h = g_h2h[wb], *h2w_l = g_h2l[wb];
        float B0h[4]={0,0,0,0}, B0l[4]={0,0,0,0}, B1h[4]={0,0,0,0}, B1l[4]={0,0,0,0};
        float D0h[4]={0,0,0,0}, D0l[4]={0,0,0,0}, D1h[4]={0,0,0,0}, D1l[4]={0,0,0,0};

        #pragma unroll
        for (int c = 0; c < 25; c++) {
            const int s = c & 1;
            // ---- compute chunk c from slot s ----
            if (c <= 7)
                compute_chunk(B0h,B0l,B1h,B1l, Ahi[s], Alo[s], b1hA + (64 + c*64)*2, b1loA + (64 + c*64)*2);
            else if (c == 8)
                compute_chunk(B0h,B0l,B1h,B1l, Ahi[s], Alo[s], b1hA, b1loA);
            else if (c <= 16)
                compute_chunk(D0h,D0l,D1h,D1l, Ahi[s], Alo[s], b2hA + (512 + (c-9)*64)*2, b2loA + (512 + (c-9)*64)*2);
            else
                compute_chunk(D0h,D0l,D1h,D1l, Ahi[s], Alo[s], b2hA + ((c-17)*64)*2, b2loA + ((c-17)*64)*2);

            // ---- gates + issue (target slot s, just freed by this compute) ----
            if (c == 2) {
                issue_chunk(Ahi[s], Alo[s], h1r_h, h1r_l, 32, (c+2)*4, rowgrp, lane);
                poll_cnt(&g_cntC, 128*t);       // h2f(t-1), h2old(t-1) ready everywhere
                if (t > 0) {
                    // Phase A(t): pred + impute cur(t)
                    const int r  = (bid & 1)*64 + (tid >> 2);
                    const int l4 = tid & 3;
                    const float* hrow = &g_h2f[rb][r*HH + l4*128];
                    const float* wv = sh_wp + l4*128;
                    float sacc0 = 0.f, sacc1 = 0.f;
                    #pragma unroll 4
                    for (int kk = 0; kk < 128; kk += 8) {
                        float4 ha = __ldcg((const float4*)(hrow + kk));
                        float4 hb = __ldcg((const float4*)(hrow + kk + 4));
                        sacc0 += ha.x*wv[kk]   + ha.y*wv[kk+1] + ha.z*wv[kk+2] + ha.w*wv[kk+3];
                        sacc1 += hb.x*wv[kk+4] + hb.y*wv[kk+5] + hb.z*wv[kk+6] + hb.w*wv[kk+7];
                    }
                    float sacc = sacc0 + sacc1;
                    sacc += __shfl_xor_sync(0xffffffffu, sacc, 2);
                    sacc += __shfl_xor_sync(0xffffffffu, sacc, 1);
                    if (l4 == 0) {
                        float p  = sacc + biasd;
                        float xv = x[(r*TT + t)*DD + dcol];
                        float cv = (xv == 128.0f) ? p : xv;
                        unsigned short chi, clo; bf16split(cv, chi, clo);
                        int ci = cfrag_idx(r, dcol);
                        g_curh[ci] = chi; g_curl[ci] = clo;
                        out[(r*(TT-1) + (t-1))*DD + dcol] = p;
                    }
                    __syncthreads();
                    if (tid == 0) { __threadfence(); atomicAdd(&g_cntA, 1); }
                }
            } else if (c <= 5) {
                issue_chunk(Ahi[s], Alo[s], h1r_h, h1r_l, 32, (c+2)*4, rowgrp, lane);
            } else if (c == 6) {
                poll_cnt(&g_cntA, 128*(t+1));   // cur(t) written everywhere
                issue_chunk(Ahi[s], Alo[s], g_curh, g_curl, 4, 0, rowgrp, lane);   // chunk 8 -> slot 0
            } else if (c <= 14) {
                issue_chunk(Ahi[s], Alo[s], h2r_h, h2r_l, 32, (c-7)*4, rowgrp, lane);
                if (c == 8) {
                    // ---- B epilogue: h1(t) ----
                    float C0[4], C1[4];
                    #pragma unroll
                    for (int q = 0; q < 4; q++) { C0[q] = B0h[q] + B0l[q]; C1[q] = B1h[q] + B1l[q]; }
                    float hout[2];
                    gates2(C0, C1, bi0, bf0, bg0, bo0, c1st, hout);
                    #pragma unroll
                    for (int h = 0; h < 2; h++) {
                        int r = crow + 8*h;
                        unsigned short hi, lo; bf16split(hout[h], hi, lo);
                        int p = hfrag_idx(r, n0 + jj);
                        h1w_h[p] = hi; h1w_l[p] = lo;
                    }
                    __syncthreads();
                    if (tid == 0) { __threadfence(); atomicAdd(&g_cntB, 1); }
                }
            } else if (c == 15) {
                poll_cnt(&g_cntB, 128*(t+1));   // h1(t) written everywhere (7 chunks of slack)
                issue_chunk(Ahi[s], Alo[s], h1w_h, h1w_l, 32, 0*4, rowgrp, lane);  // chunk 17 -> slot 1
            } else if (c <= 22) {
                issue_chunk(Ahi[s], Alo[s], h1w_h, h1w_l, 32, (c-15)*4, rowgrp, lane);
            } else if (c == 24) {
                if (t + 1 < TT) {
                    // next-step chunks 0 (slot 0) and 1 (slot 1): h1old(t+1) = h1(t)
                    issue_chunk(Ahi[0], Alo[0], h1w_h, h1w_l, 32, 0*4, rowgrp, lane);
                    issue_chunk(Ahi[1], Alo[1], h1w_h, h1w_l, 32, 1*4, rowgrp, lane);
                }
            }
            // c == 23: no issue
        }

        // ---- C epilogue: h2(t) ----
        {
            float C0[4], C1[4];
            #pragma unroll
            for (int q = 0; q < 4; q++) { C0[q] = D0h[q] + D0l[q]; C1[q] = D1h[q] + D1l[q]; }
            float hout[2];
            gates2(C0, C1, bi1, bf1, bg1, bo1, c2st, hout);
            #pragma unroll
            for (int h = 0; h < 2; h++) {
                int r = crow + 8*h;
                unsigned short hi, lo; bf16split(hout[h], hi, lo);
                int p = hfrag_idx(r, n0 + jj);
                h2w_h[p] = hi; h2w_l[p] = lo;
                g_h2f[wb][r*HH + n0 + jj] = hout[h];
                if (t == TT-1) out[PRED_SZ + r*HH + n0 + jj] = hout[h];
            }
            __syncthreads();
            if (tid == 0) { __threadfence(); atomicAdd(&g_cntC, 1); }
        }
    }

    grid_barrier();
    if (bid == 0 && tid == 0) { g_cntA = 0; g_cntB = 0; g_cntC = 0; }
}

extern "C" void kernel_launch(void* const* d_in, const int* in_sizes, int n_in,
                              void* d_out, int out_size) {
    (void)in_sizes; (void)n_in; (void)out_size;
    const float* x    = (const float*)d_in[0];
    const float* k0   = (const float*)d_in[1];
    const float* r0   = (const float*)d_in[2];
    const float* b0   = (const float*)d_in[3];
    const float* k1   = (const float*)d_in[4];
    const float* r1   = (const float*)d_in[5];
    const float* b1   = (const float*)d_in[6];
    const float* Wm   = (const float*)d_in[7];
    const float* bias = (const float*)d_in[8];
    cudaFuncSetAttribute(ajrnn_kernel, cudaFuncAttributeMaxDynamicSharedMemorySize, SM_TOTAL);
    ajrnn_kernel<<<NBLK, NTHR, SM_TOTAL>>>(x, k0, r0, b0, k1, r1, b1, Wm, bias, (float*)d_out);
}